// round 15
// baseline (speedup 1.0000x reference)
#include <cuda_runtime.h>
#include <cuda_bf16.h>
#include <cuda_fp16.h>
#include <stdint.h>

// Problem constants
#define BB 8
#define NN 2048
#define HH 512
#define NSEL 9
#define NLAYERS 3
#define LN_EPS 1e-5f

#define ADJ_WORDS 64
#define MTOT (BB*NN)        // 16384 rows
#define GRID 16             // 16x16 spatial bins
#define CW (1.0f/16.0f)

// ---------------- device scratch ----------------
__device__ uint32_t g_adj[BB * NN * ADJ_WORDS];     // 4 MB
__device__ float4   g_x4[BB * NN * (HH/4)];         // 32 MB current x (fp32, residual path)
__device__ __half   g_xh[MTOT * HH];                // 16 MB fp16 shadow of x (agg input)
__device__ __half   g_Ah[MTOT * HH];                // 16 MB agg fp16
__device__ __half   g_Wh[NLAYERS * HH * HH];        // W^T fp16  [l][n][k]
__device__ int      g_bin_start[BB][257];
__device__ uint16_t g_bin_ids[BB][NN];

// ---------------- helpers (sm_80+ only) ----------------
__device__ __forceinline__ uint32_t smem_u32(const void* p) {
    uint32_t a;
    asm("{ .reg .u64 t; cvta.to.shared.u64 t, %1; cvt.u32.u64 %0, t; }" : "=r"(a) : "l"(p));
    return a;
}
__device__ __forceinline__ void ldm_x4(uint32_t* r, uint32_t addr) {
    asm volatile("ldmatrix.sync.aligned.m8n8.x4.shared.b16 {%0,%1,%2,%3}, [%4];"
                 : "=r"(r[0]), "=r"(r[1]), "=r"(r[2]), "=r"(r[3]) : "r"(addr));
}
__device__ __forceinline__ void mma_fp16(float* c, const uint32_t* a, const uint32_t* b) {
    asm volatile("mma.sync.aligned.m16n8k16.row.col.f32.f16.f16.f32 "
                 "{%0,%1,%2,%3}, {%4,%5,%6,%7}, {%8,%9}, {%0,%1,%2,%3};"
                 : "+f"(c[0]), "+f"(c[1]), "+f"(c[2]), "+f"(c[3])
                 : "r"(a[0]), "r"(a[1]), "r"(a[2]), "r"(a[3]), "r"(b[0]), "r"(b[1]));
}
__device__ __forceinline__ void cpa16(uint32_t s, const void* g) {
    asm volatile("cp.async.cg.shared.global [%0], [%1], 16;" :: "r"(s), "l"(g));
}

// ---------------- kernel 0: merged setup ----------------
// blocks [0,128): zero g_adj
// blocks [128,896): convw (3*16*16 tiles)
// blocks [896,1920): node_features fp32 -> g_xh fp16
__global__ void __launch_bounds__(256) setup_kernel(const float* __restrict__ W,
                                                    const float4* __restrict__ nf4) {
    __shared__ float tile[32][33];
    if (blockIdx.x < 128) {
        for (int j = blockIdx.x * 256 + threadIdx.x; j < BB * NN * ADJ_WORDS; j += 128 * 256)
            g_adj[j] = 0u;
        return;
    }
    if (blockIdx.x >= 896) {
        const int base = (blockIdx.x - 896) * 256 + threadIdx.x;
        for (int j = base; j < MTOT * (HH / 4); j += 1024 * 256) {
            const float4 v = nf4[j];
            ((__half2*)g_xh)[2 * j]     = __floats2half2_rn(v.x, v.y);
            ((__half2*)g_xh)[2 * j + 1] = __floats2half2_rn(v.z, v.w);
        }
        return;
    }
    const int bid = blockIdx.x - 128;
    const int l   = bid >> 8;
    const int rem = bid & 255;
    const int n0  = (rem & 15) * 32;
    const int k0  = (rem >> 4) * 32;
    const int tx  = threadIdx.x & 31;
    const int ty  = threadIdx.x >> 5;

    #pragma unroll
    for (int i = 0; i < 4; i++)
        tile[ty + i * 8][tx] = W[(size_t)l * HH * HH + (size_t)(k0 + ty + i * 8) * HH + n0 + tx];
    __syncthreads();

    #pragma unroll
    for (int i = 0; i < 4; i++) {
        const int n = n0 + ty + i * 8;
        const int k = k0 + tx;
        g_Wh[(size_t)l * HH * HH + (size_t)n * HH + k] = __float2half_rn(tile[tx][ty + i * 8]);
    }
}

// ---------------- kernel 1: spatial binning (one block per batch) ----------------
__global__ void __launch_bounds__(256) bin_kernel(const float2* __restrict__ coords) {
    __shared__ int cnt[256];
    __shared__ int start[257];
    __shared__ uint16_t cellof[NN];
    const int b = blockIdx.x;
    const int tid = threadIdx.x;

    cnt[tid] = 0;
    __syncthreads();
    for (int i = tid; i < NN; i += 256) {
        const float2 c = coords[(size_t)b * NN + i];
        int cx = (int)(c.x * GRID); cx = cx < 0 ? 0 : (cx > 15 ? 15 : cx);
        int cy = (int)(c.y * GRID); cy = cy < 0 ? 0 : (cy > 15 ? 15 : cy);
        const int cell = cy * GRID + cx;
        cellof[i] = (uint16_t)cell;
        atomicAdd(&cnt[cell], 1);
    }
    __syncthreads();
    if (tid == 0) {
        int run = 0;
        for (int c = 0; c < 256; c++) { start[c] = run; run += cnt[c]; }
        start[256] = run;
    }
    __syncthreads();
    g_bin_start[b][tid] = start[tid];
    if (tid == 0) g_bin_start[b][256] = start[256];
    cnt[tid] = start[tid];            // reuse as scatter cursor
    __syncthreads();
    for (int i = tid; i < NN; i += 256) {
        const int cell = cellof[i];
        const int pos = atomicAdd(&cnt[cell], 1);
        g_bin_ids[b][pos] = (uint16_t)i;
    }
}

// ---------------- kernel 2: binned exact top-k + adjacency ----------------
__global__ void __launch_bounds__(256) topk_adj_kernel(const float2* __restrict__ coords) {
    __shared__ float2 sc[NN];          // 16 KB
    __shared__ int sstart[257];
    __shared__ uint16_t sids[NN];      // 4 KB
    const int b   = blockIdx.y;
    const int seg = blockIdx.x;
    const int tid = threadIdx.x;

    const float2* cb = coords + (size_t)b * NN;
    for (int i = tid; i < NN; i += 256) { sc[i] = cb[i]; sids[i] = g_bin_ids[b][i]; }
    if (tid < 128) { sstart[2*tid] = g_bin_start[b][2*tid]; sstart[2*tid+1] = g_bin_start[b][2*tid+1]; }
    if (tid == 0) sstart[256] = g_bin_start[b][256];
    __syncthreads();

    const int n = seg * 256 + tid;
    const float xn = sc[n].x, yn = sc[n].y;
    const float sqn = __fadd_rn(__fmul_rn(xn, xn), __fmul_rn(yn, yn));
    int cx = (int)(xn * GRID); cx = cx < 0 ? 0 : (cx > 15 ? 15 : cx);
    int cy = (int)(yn * GRID); cy = cy < 0 ? 0 : (cy > 15 ? 15 : cy);

    unsigned long long top[NSEL];
    #pragma unroll
    for (int j = 0; j < NSEL; j++) top[j] = ~0ull;

    #define SCAN_CELL(yy, xx) do {                                                     \
        const int c_ = (yy) * GRID + (xx);                                             \
        const int e_ = sstart[c_ + 1];                                                 \
        for (int j_ = sstart[c_]; j_ < e_; j_++) {                                     \
            const int m_ = sids[j_];                                                   \
            const float xm_ = sc[m_].x, ym_ = sc[m_].y;                                \
            const float sqm_ = __fadd_rn(__fmul_rn(xm_, xm_), __fmul_rn(ym_, ym_));    \
            const float dot_ = __fmaf_rn(yn, ym_, __fmul_rn(xn, xm_));                 \
            const float d2_  = __fsub_rn(__fadd_rn(sqn, sqm_), __fmul_rn(2.0f, dot_)); \
            uint32_t fb_ = __float_as_uint(d2_);                                       \
            fb_ = (fb_ & 0x80000000u) ? ~fb_ : (fb_ | 0x80000000u);                    \
            const unsigned long long k_ = ((unsigned long long)fb_ << 32) | (uint32_t)m_; \
            if (k_ < top[NSEL - 1]) {                                                  \
                top[NSEL - 1] = k_;                                                    \
                _Pragma("unroll")                                                      \
                for (int q_ = NSEL - 1; q_ > 0; q_--) {                                \
                    if (top[q_] < top[q_ - 1]) {                                       \
                        unsigned long long t_ = top[q_];                               \
                        top[q_] = top[q_ - 1]; top[q_ - 1] = t_;                       \
                    }                                                                  \
                }                                                                      \
            }                                                                          \
        }                                                                              \
    } while (0)

    for (int r = 1; r <= GRID; r++) {
        const int x0 = (cx - r < 0) ? 0 : cx - r;
        const int x1 = (cx + r > 15) ? 15 : cx + r;
        if (r == 1) {
            const int y0 = (cy - 1 < 0) ? 0 : cy - 1;
            const int y1 = (cy + 1 > 15) ? 15 : cy + 1;
            for (int yy = y0; yy <= y1; yy++)
                for (int xx = x0; xx <= x1; xx++) SCAN_CELL(yy, xx);
        } else {
            if (cy - r >= 0)  for (int xx = x0; xx <= x1; xx++) SCAN_CELL(cy - r, xx);
            if (cy + r <= 15) for (int xx = x0; xx <= x1; xx++) SCAN_CELL(cy + r, xx);
            const int yi0 = (cy - r + 1 < 0) ? 0 : cy - r + 1;
            const int yi1 = (cy + r - 1 > 15) ? 15 : cy + r - 1;
            if (cx - r >= 0)  for (int yy = yi0; yy <= yi1; yy++) SCAN_CELL(yy, cx - r);
            if (cx + r <= 15) for (int yy = yi0; yy <= yi1; yy++) SCAN_CELL(yy, cx + r);
        }
        if (cx - r <= 0 && cx + r >= 15 && cy - r <= 0 && cy + r >= 15) break;
        float bnd = 1e30f;
        if (cx - r > 0)  bnd = fminf(bnd, xn - (float)(cx - r) * CW);
        if (cx + r < 15) bnd = fminf(bnd, (float)(cx + r + 1) * CW - xn);
        if (cy - r > 0)  bnd = fminf(bnd, yn - (float)(cy - r) * CW);
        if (cy + r < 15) bnd = fminf(bnd, (float)(cy + r + 1) * CW - yn);
        if (top[NSEL - 1] != ~0ull) {
            const uint32_t fb8 = (uint32_t)(top[NSEL - 1] >> 32);
            const float kd = (fb8 & 0x80000000u) ? __uint_as_float(fb8 ^ 0x80000000u)
                                                 : __uint_as_float(~fb8);
            if (kd < bnd * bnd - 1e-4f) break;
        }
    }

    #pragma unroll
    for (int rr = 1; rr < NSEL; rr++) {
        const int m = (int)(top[rr] & 0xffffffffu);
        atomicOr(&g_adj[((size_t)b * NN + n) * ADJ_WORDS + (m >> 5)], 1u << (m & 31));
        atomicOr(&g_adj[((size_t)b * NN + m) * ADJ_WORDS + (n >> 5)], 1u << (n & 31));
    }
}

// ---------------- kernel 3: sparse aggregation over fp16 shadow ----------------
__global__ void __launch_bounds__(128) agg_kernel() {
    __shared__ uint32_t rowbits[ADJ_WORDS];
    __shared__ int s_off[ADJ_WORDS];
    __shared__ int s_nbr[512];
    __shared__ int s_cnt;
    const int b = blockIdx.y;
    const int n = blockIdx.x;
    const int t = threadIdx.x;

    const uint32_t* row = &g_adj[((size_t)b * NN + n) * ADJ_WORDS];
    if (t < ADJ_WORDS) rowbits[t] = row[t];
    __syncthreads();

    if (t == 0) {
        int off = 0;
        #pragma unroll
        for (int w = 0; w < ADJ_WORDS; w++) { s_off[w] = off; off += __popc(rowbits[w]); }
        s_cnt = off;
    }
    __syncthreads();
    if (t < ADJ_WORDS) {
        uint32_t bits = rowbits[t];
        int pos = s_off[t];
        while (bits) {
            const int bit = __ffs(bits) - 1;
            bits &= bits - 1;
            s_nbr[pos++] = (t << 5) + bit;
        }
    }
    __syncthreads();

    const int deg = s_cnt;
    const uint2* xb = (const uint2*)(g_xh + (size_t)b * NN * HH);
    float4 acc = make_float4(0.f, 0.f, 0.f, 0.f);
    for (int i = 0; i < deg; i++) {
        const uint2 v = __ldg(&xb[(size_t)s_nbr[i] * (HH/4) + t]);
        const float2 f01 = __half22float2(*(const __half2*)&v.x);
        const float2 f23 = __half22float2(*(const __half2*)&v.y);
        acc.x += f01.x; acc.y += f01.y; acc.z += f23.x; acc.w += f23.y;
    }

    __half2 h01 = __halves2half2(__float2half_rn(acc.x), __float2half_rn(acc.y));
    __half2 h23 = __halves2half2(__float2half_rn(acc.z), __float2half_rn(acc.w));
    const size_t base = ((size_t)b * NN + n) * (HH/2) + 2 * t;
    ((__half2*)g_Ah)[base]     = h01;
    ((__half2*)g_Ah)[base + 1] = h23;
}

// ---------------- kernel 4: cp.async-pipelined fp16 GEMM + LN, K-chunk 64 (R14) --
#define STG      82944
#define SG_BIAS  165888
#define SG_GAMMA 167936
#define SG_BETA  169984
#define SG_PSUM  172032
#define SG_PSQ   174080
#define SG_MU    176128
#define SG_RS    176384
#define SM_TOTAL2 176640

__global__ void __launch_bounds__(512, 1) gemm_mma_kernel(
    const __half* __restrict__ Ah,
    const __half* __restrict__ Wh,
    const float* __restrict__ bl, const float* __restrict__ gl, const float* __restrict__ btl,
    const float* __restrict__ resid, float* __restrict__ out, __half* __restrict__ outh)
{
    extern __shared__ char smem[];
    const uint32_t sbase = smem_u32(smem);
    const int tid  = threadIdx.x;
    const int lane = tid & 31;
    const int wid  = tid >> 5;
    const int mwarp = wid >> 3;
    const int nwarp = wid & 7;
    const int row0 = blockIdx.x * 64;

    ((float*)(smem + SG_BIAS))[tid]  = __ldg(&bl[tid]);
    ((float*)(smem + SG_GAMMA))[tid] = __ldg(&gl[tid]);
    ((float*)(smem + SG_BETA))[tid]  = __ldg(&btl[tid]);

    float c[16][4];
    #pragma unroll
    for (int f = 0; f < 16; f++)
        #pragma unroll
        for (int q = 0; q < 4; q++) c[f][q] = 0.f;

    #define LOAD_CHUNK(chk, stg) do {                                              \
        const int kc0_ = (chk) * 64;                                               \
        const uint32_t sb_ = sbase + (stg) * STG;                                  \
        {                                                                          \
            const int r_ = tid >> 3, seg_ = tid & 7;                               \
            cpa16(sb_ + r_ * 144 + seg_ * 16,                                      \
                  Ah + (size_t)(row0 + r_) * HH + kc0_ + seg_ * 8);                \
        }                                                                          \
        _Pragma("unroll")                                                          \
        for (int i_ = 0; i_ < 8; i_++) {                                           \
            const int idx_ = tid + i_ * 512;                                       \
            const int r_ = idx_ >> 3, seg_ = idx_ & 7;                             \
            cpa16(sb_ + 9216 + r_ * 144 + seg_ * 16,                               \
                  Wh + (size_t)r_ * HH + kc0_ + seg_ * 8);                         \
        }                                                                          \
        asm volatile("cp.async.commit_group;");                                    \
    } while (0)

    LOAD_CHUNK(0, 0);

    for (int chk = 0; chk < 8; chk++) {
        if (chk + 1 < 8) {
            LOAD_CHUNK(chk + 1, (chk + 1) & 1);
            asm volatile("cp.async.wait_group 1;");
        } else {
            asm volatile("cp.async.wait_group 0;");
        }
        __syncthreads();

        const uint32_t sb = sbase + (chk & 1) * STG;
        #pragma unroll
        for (int ks = 0; ks < 4; ks++) {
            const int amat = lane >> 3;
            const int arow = (amat & 1) * 8 + (lane & 7);
            const int akb  = (ks * 16 + (amat >> 1) * 8) * 2;
            uint32_t ah[2][4], bb[8][2];
            #pragma unroll
            for (int mi = 0; mi < 2; mi++) {
                const uint32_t ra = mwarp * 32 + mi * 16 + arow;
                ldm_x4(ah[mi], sb + ra * 144 + akb);
            }
            const int bmat = lane >> 3;
            const int bn   = (bmat >> 1) * 8 + (lane & 7);
            const int bkb  = (ks * 16 + (bmat & 1) * 8) * 2;
            #pragma unroll
            for (int g = 0; g < 4; g++) {
                uint32_t r[4];
                ldm_x4(r, sb + 9216 + (uint32_t)(nwarp * 64 + g * 16 + bn) * 144 + bkb);
                bb[g*2][0] = r[0]; bb[g*2][1] = r[1];
                bb[g*2+1][0] = r[2]; bb[g*2+1][1] = r[3];
            }
            #pragma unroll
            for (int mi = 0; mi < 2; mi++)
                #pragma unroll
                for (int ni = 0; ni < 8; ni++) mma_fp16(c[mi*8+ni], ah[mi], bb[ni]);
        }
        __syncthreads();
    }

    // ---------------- epilogue ----------------
    float* bias_s  = (float*)(smem + SG_BIAS);
    float* gamma_s = (float*)(smem + SG_GAMMA);
    float* beta_s  = (float*)(smem + SG_BETA);
    float* psum_s  = (float*)(smem + SG_PSUM);
    float* psq_s   = (float*)(smem + SG_PSQ);
    float* mu_s    = (float*)(smem + SG_MU);
    float* rs_s    = (float*)(smem + SG_RS);

    float ps[2][2] = {{0.f,0.f},{0.f,0.f}};
    float pq[2][2] = {{0.f,0.f},{0.f,0.f}};
    #pragma unroll
    for (int mi = 0; mi < 2; mi++)
        #pragma unroll
        for (int ni = 0; ni < 8; ni++) {
            const int f = mi*8 + ni;
            #pragma unroll
            for (int h = 0; h < 2; h++)
                #pragma unroll
                for (int j = 0; j < 2; j++) {
                    const int col = nwarp*64 + ni*8 + (lane & 3)*2 + j;
                    const float v = c[f][h*2+j] + bias_s[col];
                    c[f][h*2+j] = v;
                    ps[mi][h] += v;
                    pq[mi][h] += v * v;
                }
        }
    #pragma unroll
    for (int mi = 0; mi < 2; mi++)
        #pragma unroll
        for (int h = 0; h < 2; h++) {
            #pragma unroll
            for (int off = 1; off < 4; off <<= 1) {
                ps[mi][h] += __shfl_xor_sync(0xffffffffu, ps[mi][h], off);
                pq[mi][h] += __shfl_xor_sync(0xffffffffu, pq[mi][h], off);
            }
        }
    if ((lane & 3) == 0) {
        #pragma unroll
        for (int mi = 0; mi < 2; mi++)
            #pragma unroll
            for (int h = 0; h < 2; h++) {
                const int rl = mwarp*32 + mi*16 + h*8 + (lane >> 2);
                psum_s[rl*8 + nwarp] = ps[mi][h];
                psq_s [rl*8 + nwarp] = pq[mi][h];
            }
    }
    __syncthreads();
    if (tid < 64) {
        float s = 0.f, q = 0.f;
        #pragma unroll
        for (int w = 0; w < 8; w++) { s += psum_s[tid*8 + w]; q += psq_s[tid*8 + w]; }
        const float mu = s * (1.0f / HH);
        const float var = q * (1.0f / HH) - mu * mu;
        mu_s[tid] = mu;
        rs_s[tid] = rsqrtf(var + LN_EPS);
    }
    __syncthreads();

    #pragma unroll
    for (int mi = 0; mi < 2; mi++)
        #pragma unroll
        for (int h = 0; h < 2; h++) {
            const int rl = mwarp*32 + mi*16 + h*8 + (lane >> 2);
            const int grow = row0 + rl;
            const float mu = mu_s[rl];
            const float rs = rs_s[rl];
            #pragma unroll
            for (int ni = 0; ni < 8; ni++) {
                const int f = mi*8 + ni;
                const int col = nwarp*64 + ni*8 + (lane & 3)*2;
                float2 o;
                o.x = fmaxf((c[f][h*2+0] - mu) * rs * gamma_s[col]   + beta_s[col],   0.f);
                o.y = fmaxf((c[f][h*2+1] - mu) * rs * gamma_s[col+1] + beta_s[col+1], 0.f);
                if (resid != nullptr) {
                    const float2 rv = __ldg((const float2*)&resid[(size_t)grow * HH + col]);
                    o.x += rv.x; o.y += rv.y;
                }
                *(float2*)&out[(size_t)grow * HH + col] = o;
                if (outh != nullptr)
                    *(__half2*)&outh[(size_t)grow * HH + col] = __floats2half2_rn(o.x, o.y);
            }
        }
}

// ---------------- launcher ----------------
extern "C" void kernel_launch(void* const* d_in, const int* in_sizes, int n_in,
                              void* d_out, int out_size) {
    (void)in_sizes; (void)n_in; (void)out_size;
    const float*  node_features = (const float*)d_in[0];   // [8,2048,512]
    const float2* coords        = (const float2*)d_in[1];  // [8,2048,2]
    const float*  W             = (const float*)d_in[2];   // [3,512,512]
    const float*  bvec          = (const float*)d_in[3];   // [3,512]
    const float*  gamma         = (const float*)d_in[4];   // [3,512]
    const float*  beta          = (const float*)d_in[5];   // [3,512]
    float*        outp          = (float*)d_out;           // [8,2048,512]

    float4* gx;  cudaGetSymbolAddress((void**)&gx,  g_x4);
    __half *ah, *wh, *xh;
    cudaGetSymbolAddress((void**)&ah, g_Ah);
    cudaGetSymbolAddress((void**)&wh, g_Wh);
    cudaGetSymbolAddress((void**)&xh, g_xh);

    cudaFuncSetAttribute(gemm_mma_kernel, cudaFuncAttributeMaxDynamicSharedMemorySize, SM_TOTAL2);

    setup_kernel<<<1920, 256>>>(W, (const float4*)node_features);
    bin_kernel<<<BB, 256>>>(coords);
    topk_adj_kernel<<<dim3(NN / 256, BB), 256>>>(coords);

    for (int l = 0; l < NLAYERS; l++) {
        agg_kernel<<<dim3(NN, BB), 128>>>();

        const float* resid = (l == 0) ? nullptr : (const float*)gx;
        float* out = (l == NLAYERS - 1) ? outp : (float*)gx;
        __half* outh = (l == NLAYERS - 1) ? ((__half*)nullptr) : xh;
        gemm_mma_kernel<<<MTOT / 64, 512, SM_TOTAL2>>>(
            ah, wh + (size_t)l * HH * HH,
            bvec + (size_t)l * HH, gamma + (size_t)l * HH, beta + (size_t)l * HH,
            resid, out, outh);
    }
}

// round 16
// speedup vs baseline: 1.0469x; 1.0469x over previous
#include <cuda_runtime.h>
#include <cuda_bf16.h>
#include <cuda_fp16.h>
#include <stdint.h>

// Problem constants
#define BB 8
#define NN 2048
#define HH 512
#define NSEL 9
#define NLAYERS 3
#define LN_EPS 1e-5f

#define ADJ_WORDS 64
#define MTOT (BB*NN)        // 16384 rows
#define GRID 16             // 16x16 spatial bins
#define CW (1.0f/16.0f)
#define MAXD 64             // provable 2D kNN degree bound: 6k+k = 56 < 64

// ---------------- device scratch ----------------
__device__ uint32_t g_adj[BB * NN * ADJ_WORDS];     // 4 MB
__device__ float4   g_x4[BB * NN * (HH/4)];         // 32 MB current x (fp32, residual path)
__device__ __half   g_Ah[MTOT * HH];                // 16 MB agg fp16
__device__ __half   g_Wh[NLAYERS * HH * HH];        // W^T fp16  [l][n][k]
__device__ int      g_bin_start[BB][257];
__device__ uint16_t g_bin_ids[BB][NN];
__device__ uint16_t g_nbr[MTOT * MAXD];             // 2 MB CSR neighbor ids
__device__ int      g_deg[MTOT];

// ---------------- helpers (sm_80+ only) ----------------
__device__ __forceinline__ uint32_t smem_u32(const void* p) {
    uint32_t a;
    asm("{ .reg .u64 t; cvta.to.shared.u64 t, %1; cvt.u32.u64 %0, t; }" : "=r"(a) : "l"(p));
    return a;
}
__device__ __forceinline__ void ldm_x4(uint32_t* r, uint32_t addr) {
    asm volatile("ldmatrix.sync.aligned.m8n8.x4.shared.b16 {%0,%1,%2,%3}, [%4];"
                 : "=r"(r[0]), "=r"(r[1]), "=r"(r[2]), "=r"(r[3]) : "r"(addr));
}
__device__ __forceinline__ void mma_fp16(float* c, const uint32_t* a, const uint32_t* b) {
    asm volatile("mma.sync.aligned.m16n8k16.row.col.f32.f16.f16.f32 "
                 "{%0,%1,%2,%3}, {%4,%5,%6,%7}, {%8,%9}, {%0,%1,%2,%3};"
                 : "+f"(c[0]), "+f"(c[1]), "+f"(c[2]), "+f"(c[3])
                 : "r"(a[0]), "r"(a[1]), "r"(a[2]), "r"(a[3]), "r"(b[0]), "r"(b[1]));
}
__device__ __forceinline__ void cpa16(uint32_t s, const void* g) {
    asm volatile("cp.async.cg.shared.global [%0], [%1], 16;" :: "r"(s), "l"(g));
}

// ---------------- kernel 0: merged setup (zero adjacency + W transpose/fp16) ----
__global__ void __launch_bounds__(256) setup_kernel(const float* __restrict__ W) {
    __shared__ float tile[32][33];
    if (blockIdx.x < 128) {
        for (int j = blockIdx.x * 256 + threadIdx.x; j < BB * NN * ADJ_WORDS; j += 128 * 256)
            g_adj[j] = 0u;
        return;
    }
    const int bid = blockIdx.x - 128;
    const int l   = bid >> 8;
    const int rem = bid & 255;
    const int n0  = (rem & 15) * 32;
    const int k0  = (rem >> 4) * 32;
    const int tx  = threadIdx.x & 31;
    const int ty  = threadIdx.x >> 5;

    #pragma unroll
    for (int i = 0; i < 4; i++)
        tile[ty + i * 8][tx] = W[(size_t)l * HH * HH + (size_t)(k0 + ty + i * 8) * HH + n0 + tx];
    __syncthreads();

    #pragma unroll
    for (int i = 0; i < 4; i++) {
        const int n = n0 + ty + i * 8;
        const int k = k0 + tx;
        g_Wh[(size_t)l * HH * HH + (size_t)n * HH + k] = __float2half_rn(tile[tx][ty + i * 8]);
    }
}

// ---------------- kernel 1: spatial binning (one block per batch) ----------------
__global__ void __launch_bounds__(256) bin_kernel(const float2* __restrict__ coords) {
    __shared__ int cnt[256];
    __shared__ int start[257];
    __shared__ uint16_t cellof[NN];
    const int b = blockIdx.x;
    const int tid = threadIdx.x;

    cnt[tid] = 0;
    __syncthreads();
    for (int i = tid; i < NN; i += 256) {
        const float2 c = coords[(size_t)b * NN + i];
        int cx = (int)(c.x * GRID); cx = cx < 0 ? 0 : (cx > 15 ? 15 : cx);
        int cy = (int)(c.y * GRID); cy = cy < 0 ? 0 : (cy > 15 ? 15 : cy);
        const int cell = cy * GRID + cx;
        cellof[i] = (uint16_t)cell;
        atomicAdd(&cnt[cell], 1);
    }
    __syncthreads();
    if (tid == 0) {
        int run = 0;
        for (int c = 0; c < 256; c++) { start[c] = run; run += cnt[c]; }
        start[256] = run;
    }
    __syncthreads();
    g_bin_start[b][tid] = start[tid];
    if (tid == 0) g_bin_start[b][256] = start[256];
    cnt[tid] = start[tid];            // reuse as scatter cursor
    __syncthreads();
    for (int i = tid; i < NN; i += 256) {
        const int cell = cellof[i];
        const int pos = atomicAdd(&cnt[cell], 1);
        g_bin_ids[b][pos] = (uint16_t)i;
    }
}

// ---------------- kernel 2: binned exact top-k + adjacency ----------------
__global__ void __launch_bounds__(256) topk_adj_kernel(const float2* __restrict__ coords) {
    __shared__ float2 sc[NN];          // 16 KB
    __shared__ int sstart[257];
    __shared__ uint16_t sids[NN];      // 4 KB
    const int b   = blockIdx.y;
    const int seg = blockIdx.x;
    const int tid = threadIdx.x;

    const float2* cb = coords + (size_t)b * NN;
    for (int i = tid; i < NN; i += 256) { sc[i] = cb[i]; sids[i] = g_bin_ids[b][i]; }
    if (tid < 128) { sstart[2*tid] = g_bin_start[b][2*tid]; sstart[2*tid+1] = g_bin_start[b][2*tid+1]; }
    if (tid == 0) sstart[256] = g_bin_start[b][256];
    __syncthreads();

    const int n = seg * 256 + tid;
    const float xn = sc[n].x, yn = sc[n].y;
    const float sqn = __fadd_rn(__fmul_rn(xn, xn), __fmul_rn(yn, yn));
    int cx = (int)(xn * GRID); cx = cx < 0 ? 0 : (cx > 15 ? 15 : cx);
    int cy = (int)(yn * GRID); cy = cy < 0 ? 0 : (cy > 15 ? 15 : cy);

    unsigned long long top[NSEL];
    #pragma unroll
    for (int j = 0; j < NSEL; j++) top[j] = ~0ull;

    #define SCAN_CELL(yy, xx) do {                                                     \
        const int c_ = (yy) * GRID + (xx);                                             \
        const int e_ = sstart[c_ + 1];                                                 \
        for (int j_ = sstart[c_]; j_ < e_; j_++) {                                     \
            const int m_ = sids[j_];                                                   \
            const float xm_ = sc[m_].x, ym_ = sc[m_].y;                                \
            const float sqm_ = __fadd_rn(__fmul_rn(xm_, xm_), __fmul_rn(ym_, ym_));    \
            const float dot_ = __fmaf_rn(yn, ym_, __fmul_rn(xn, xm_));                 \
            const float d2_  = __fsub_rn(__fadd_rn(sqn, sqm_), __fmul_rn(2.0f, dot_)); \
            uint32_t fb_ = __float_as_uint(d2_);                                       \
            fb_ = (fb_ & 0x80000000u) ? ~fb_ : (fb_ | 0x80000000u);                    \
            const unsigned long long k_ = ((unsigned long long)fb_ << 32) | (uint32_t)m_; \
            if (k_ < top[NSEL - 1]) {                                                  \
                top[NSEL - 1] = k_;                                                    \
                _Pragma("unroll")                                                      \
                for (int q_ = NSEL - 1; q_ > 0; q_--) {                                \
                    if (top[q_] < top[q_ - 1]) {                                       \
                        unsigned long long t_ = top[q_];                               \
                        top[q_] = top[q_ - 1]; top[q_ - 1] = t_;                       \
                    }                                                                  \
                }                                                                      \
            }                                                                          \
        }                                                                              \
    } while (0)

    for (int r = 1; r <= GRID; r++) {
        const int x0 = (cx - r < 0) ? 0 : cx - r;
        const int x1 = (cx + r > 15) ? 15 : cx + r;
        if (r == 1) {
            const int y0 = (cy - 1 < 0) ? 0 : cy - 1;
            const int y1 = (cy + 1 > 15) ? 15 : cy + 1;
            for (int yy = y0; yy <= y1; yy++)
                for (int xx = x0; xx <= x1; xx++) SCAN_CELL(yy, xx);
        } else {
            if (cy - r >= 0)  for (int xx = x0; xx <= x1; xx++) SCAN_CELL(cy - r, xx);
            if (cy + r <= 15) for (int xx = x0; xx <= x1; xx++) SCAN_CELL(cy + r, xx);
            const int yi0 = (cy - r + 1 < 0) ? 0 : cy - r + 1;
            const int yi1 = (cy + r - 1 > 15) ? 15 : cy + r - 1;
            if (cx - r >= 0)  for (int yy = yi0; yy <= yi1; yy++) SCAN_CELL(yy, cx - r);
            if (cx + r <= 15) for (int yy = yi0; yy <= yi1; yy++) SCAN_CELL(yy, cx + r);
        }
        if (cx - r <= 0 && cx + r >= 15 && cy - r <= 0 && cy + r >= 15) break;
        float bnd = 1e30f;
        if (cx - r > 0)  bnd = fminf(bnd, xn - (float)(cx - r) * CW);
        if (cx + r < 15) bnd = fminf(bnd, (float)(cx + r + 1) * CW - xn);
        if (cy - r > 0)  bnd = fminf(bnd, yn - (float)(cy - r) * CW);
        if (cy + r < 15) bnd = fminf(bnd, (float)(cy + r + 1) * CW - yn);
        if (top[NSEL - 1] != ~0ull) {
            const uint32_t fb8 = (uint32_t)(top[NSEL - 1] >> 32);
            const float kd = (fb8 & 0x80000000u) ? __uint_as_float(fb8 ^ 0x80000000u)
                                                 : __uint_as_float(~fb8);
            if (kd < bnd * bnd - 1e-4f) break;
        }
    }

    #pragma unroll
    for (int rr = 1; rr < NSEL; rr++) {
        const int m = (int)(top[rr] & 0xffffffffu);
        atomicOr(&g_adj[((size_t)b * NN + n) * ADJ_WORDS + (m >> 5)], 1u << (m & 31));
        atomicOr(&g_adj[((size_t)b * NN + m) * ADJ_WORDS + (n >> 5)], 1u << (n & 31));
    }
}

// ---------------- kernel 3: bitmask -> fixed-width CSR (ONCE) ----------------
// Ascending word/bit order == previous decode order -> identical agg summation.
__global__ void __launch_bounds__(256) adj2csr_kernel() {
    const int idx = blockIdx.x * 256 + threadIdx.x;   // 0..16383
    const uint32_t* row = &g_adj[(size_t)idx * ADJ_WORDS];
    int dg = 0;
    #pragma unroll 8
    for (int w = 0; w < ADJ_WORDS; w++) {
        uint32_t bits = __ldg(&row[w]);
        while (bits) {
            const int bit = __ffs(bits) - 1;
            bits &= bits - 1;
            if (dg < MAXD) g_nbr[(size_t)idx * MAXD + dg] = (uint16_t)((w << 5) + bit);
            dg++;
        }
    }
    g_deg[idx] = (dg < MAXD) ? dg : MAXD;
}

// ---------------- kernel 4: CSR sparse aggregation (fp32 in, fp16 out) ----------
__global__ void __launch_bounds__(128) agg_kernel(const float4* __restrict__ xin) {
    __shared__ uint16_t s_nbr[MAXD];
    __shared__ int s_deg;
    const int b = blockIdx.y;
    const int n = blockIdx.x;
    const int t = threadIdx.x;
    const int idx = b * NN + n;

    if (t == 0) s_deg = g_deg[idx];
    if (t < MAXD) s_nbr[t] = g_nbr[(size_t)idx * MAXD + t];
    __syncthreads();

    const int deg = s_deg;
    const float4* xb = xin + (size_t)b * NN * (HH/4);
    float4 acc = make_float4(0.f, 0.f, 0.f, 0.f);
    #pragma unroll 2
    for (int i = 0; i < deg; i++) {
        const float4 v = __ldg(&xb[(size_t)s_nbr[i] * (HH/4) + t]);
        acc.x += v.x; acc.y += v.y; acc.z += v.z; acc.w += v.w;
    }

    __half2 h01 = __halves2half2(__float2half_rn(acc.x), __float2half_rn(acc.y));
    __half2 h23 = __halves2half2(__float2half_rn(acc.z), __float2half_rn(acc.w));
    const size_t base = ((size_t)b * NN + n) * (HH/2) + 2 * t;
    ((__half2*)g_Ah)[base]     = h01;
    ((__half2*)g_Ah)[base + 1] = h23;
}

// ---------------- kernel 5: cp.async-pipelined fp16 GEMM + LN, K-chunk 64 (R14) --
#define STG      82944
#define SG_BIAS  165888
#define SG_GAMMA 167936
#define SG_BETA  169984
#define SG_PSUM  172032
#define SG_PSQ   174080
#define SG_MU    176128
#define SG_RS    176384
#define SM_TOTAL2 176640

__global__ void __launch_bounds__(512, 1) gemm_mma_kernel(
    const __half* __restrict__ Ah,
    const __half* __restrict__ Wh,
    const float* __restrict__ bl, const float* __restrict__ gl, const float* __restrict__ btl,
    const float* __restrict__ resid, float* __restrict__ out)
{
    extern __shared__ char smem[];
    const uint32_t sbase = smem_u32(smem);
    const int tid  = threadIdx.x;
    const int lane = tid & 31;
    const int wid  = tid >> 5;
    const int mwarp = wid >> 3;
    const int nwarp = wid & 7;
    const int row0 = blockIdx.x * 64;

    ((float*)(smem + SG_BIAS))[tid]  = __ldg(&bl[tid]);
    ((float*)(smem + SG_GAMMA))[tid] = __ldg(&gl[tid]);
    ((float*)(smem + SG_BETA))[tid]  = __ldg(&btl[tid]);

    float c[16][4];
    #pragma unroll
    for (int f = 0; f < 16; f++)
        #pragma unroll
        for (int q = 0; q < 4; q++) c[f][q] = 0.f;

    #define LOAD_CHUNK(chk, stg) do {                                              \
        const int kc0_ = (chk) * 64;                                               \
        const uint32_t sb_ = sbase + (stg) * STG;                                  \
        {                                                                          \
            const int r_ = tid >> 3, seg_ = tid & 7;                               \
            cpa16(sb_ + r_ * 144 + seg_ * 16,                                      \
                  Ah + (size_t)(row0 + r_) * HH + kc0_ + seg_ * 8);                \
        }                                                                          \
        _Pragma("unroll")                                                          \
        for (int i_ = 0; i_ < 8; i_++) {                                           \
            const int idx_ = tid + i_ * 512;                                       \
            const int r_ = idx_ >> 3, seg_ = idx_ & 7;                             \
            cpa16(sb_ + 9216 + r_ * 144 + seg_ * 16,                               \
                  Wh + (size_t)r_ * HH + kc0_ + seg_ * 8);                         \
        }                                                                          \
        asm volatile("cp.async.commit_group;");                                    \
    } while (0)

    LOAD_CHUNK(0, 0);

    for (int chk = 0; chk < 8; chk++) {
        if (chk + 1 < 8) {
            LOAD_CHUNK(chk + 1, (chk + 1) & 1);
            asm volatile("cp.async.wait_group 1;");
        } else {
            asm volatile("cp.async.wait_group 0;");
        }
        __syncthreads();

        const uint32_t sb = sbase + (chk & 1) * STG;
        #pragma unroll
        for (int ks = 0; ks < 4; ks++) {
            const int amat = lane >> 3;
            const int arow = (amat & 1) * 8 + (lane & 7);
            const int akb  = (ks * 16 + (amat >> 1) * 8) * 2;
            uint32_t ah[2][4], bb[8][2];
            #pragma unroll
            for (int mi = 0; mi < 2; mi++) {
                const uint32_t ra = mwarp * 32 + mi * 16 + arow;
                ldm_x4(ah[mi], sb + ra * 144 + akb);
            }
            const int bmat = lane >> 3;
            const int bn   = (bmat >> 1) * 8 + (lane & 7);
            const int bkb  = (ks * 16 + (bmat & 1) * 8) * 2;
            #pragma unroll
            for (int g = 0; g < 4; g++) {
                uint32_t r[4];
                ldm_x4(r, sb + 9216 + (uint32_t)(nwarp * 64 + g * 16 + bn) * 144 + bkb);
                bb[g*2][0] = r[0]; bb[g*2][1] = r[1];
                bb[g*2+1][0] = r[2]; bb[g*2+1][1] = r[3];
            }
            #pragma unroll
            for (int mi = 0; mi < 2; mi++)
                #pragma unroll
                for (int ni = 0; ni < 8; ni++) mma_fp16(c[mi*8+ni], ah[mi], bb[ni]);
        }
        __syncthreads();
    }

    // ---------------- epilogue ----------------
    float* bias_s  = (float*)(smem + SG_BIAS);
    float* gamma_s = (float*)(smem + SG_GAMMA);
    float* beta_s  = (float*)(smem + SG_BETA);
    float* psum_s  = (float*)(smem + SG_PSUM);
    float* psq_s   = (float*)(smem + SG_PSQ);
    float* mu_s    = (float*)(smem + SG_MU);
    float* rs_s    = (float*)(smem + SG_RS);

    float ps[2][2] = {{0.f,0.f},{0.f,0.f}};
    float pq[2][2] = {{0.f,0.f},{0.f,0.f}};
    #pragma unroll
    for (int mi = 0; mi < 2; mi++)
        #pragma unroll
        for (int ni = 0; ni < 8; ni++) {
            const int f = mi*8 + ni;
            #pragma unroll
            for (int h = 0; h < 2; h++)
                #pragma unroll
                for (int j = 0; j < 2; j++) {
                    const int col = nwarp*64 + ni*8 + (lane & 3)*2 + j;
                    const float v = c[f][h*2+j] + bias_s[col];
                    c[f][h*2+j] = v;
                    ps[mi][h] += v;
                    pq[mi][h] += v * v;
                }
        }
    #pragma unroll
    for (int mi = 0; mi < 2; mi++)
        #pragma unroll
        for (int h = 0; h < 2; h++) {
            #pragma unroll
            for (int off = 1; off < 4; off <<= 1) {
                ps[mi][h] += __shfl_xor_sync(0xffffffffu, ps[mi][h], off);
                pq[mi][h] += __shfl_xor_sync(0xffffffffu, pq[mi][h], off);
            }
        }
    if ((lane & 3) == 0) {
        #pragma unroll
        for (int mi = 0; mi < 2; mi++)
            #pragma unroll
            for (int h = 0; h < 2; h++) {
                const int rl = mwarp*32 + mi*16 + h*8 + (lane >> 2);
                psum_s[rl*8 + nwarp] = ps[mi][h];
                psq_s [rl*8 + nwarp] = pq[mi][h];
            }
    }
    __syncthreads();
    if (tid < 64) {
        float s = 0.f, q = 0.f;
        #pragma unroll
        for (int w = 0; w < 8; w++) { s += psum_s[tid*8 + w]; q += psq_s[tid*8 + w]; }
        const float mu = s * (1.0f / HH);
        const float var = q * (1.0f / HH) - mu * mu;
        mu_s[tid] = mu;
        rs_s[tid] = rsqrtf(var + LN_EPS);
    }
    __syncthreads();

    #pragma unroll
    for (int mi = 0; mi < 2; mi++)
        #pragma unroll
        for (int h = 0; h < 2; h++) {
            const int rl = mwarp*32 + mi*16 + h*8 + (lane >> 2);
            const int grow = row0 + rl;
            const float mu = mu_s[rl];
            const float rs = rs_s[rl];
            #pragma unroll
            for (int ni = 0; ni < 8; ni++) {
                const int f = mi*8 + ni;
                const int col = nwarp*64 + ni*8 + (lane & 3)*2;
                float2 o;
                o.x = fmaxf((c[f][h*2+0] - mu) * rs * gamma_s[col]   + beta_s[col],   0.f);
                o.y = fmaxf((c[f][h*2+1] - mu) * rs * gamma_s[col+1] + beta_s[col+1], 0.f);
                if (resid != nullptr) {
                    const float2 rv = __ldg((const float2*)&resid[(size_t)grow * HH + col]);
                    o.x += rv.x; o.y += rv.y;
                }
                *(float2*)&out[(size_t)grow * HH + col] = o;
            }
        }
}

// ---------------- launcher ----------------
extern "C" void kernel_launch(void* const* d_in, const int* in_sizes, int n_in,
                              void* d_out, int out_size) {
    (void)in_sizes; (void)n_in; (void)out_size;
    const float*  node_features = (const float*)d_in[0];   // [8,2048,512]
    const float2* coords        = (const float2*)d_in[1];  // [8,2048,2]
    const float*  W             = (const float*)d_in[2];   // [3,512,512]
    const float*  bvec          = (const float*)d_in[3];   // [3,512]
    const float*  gamma         = (const float*)d_in[4];   // [3,512]
    const float*  beta          = (const float*)d_in[5];   // [3,512]
    float*        outp          = (float*)d_out;           // [8,2048,512]

    float4* gx;  cudaGetSymbolAddress((void**)&gx,  g_x4);
    __half *ah, *wh;
    cudaGetSymbolAddress((void**)&ah, g_Ah);
    cudaGetSymbolAddress((void**)&wh, g_Wh);

    cudaFuncSetAttribute(gemm_mma_kernel, cudaFuncAttributeMaxDynamicSharedMemorySize, SM_TOTAL2);

    setup_kernel<<<896, 256>>>(W);
    bin_kernel<<<BB, 256>>>(coords);
    topk_adj_kernel<<<dim3(NN / 256, BB), 256>>>(coords);
    adj2csr_kernel<<<MTOT / 256, 256>>>();

    for (int l = 0; l < NLAYERS; l++) {
        const float4* xin = (l == 0) ? (const float4*)node_features : (const float4*)gx;
        agg_kernel<<<dim3(NN, BB), 128>>>(xin);

        const float* resid = (l == 0) ? nullptr : (const float*)gx;
        float* out = (l == NLAYERS - 1) ? outp : (float*)gx;
        gemm_mma_kernel<<<MTOT / 64, 512, SM_TOTAL2>>>(
            ah, wh + (size_t)l * HH * HH,
            bvec + (size_t)l * HH, gamma + (size_t)l * HH, beta + (size_t)l * HH,
            resid, out);
    }
}

// round 17
// speedup vs baseline: 1.1019x; 1.0525x over previous
#include <cuda_runtime.h>
#include <cuda_bf16.h>
#include <cuda_fp16.h>
#include <stdint.h>

// Problem constants
#define BB 8
#define NN 2048
#define HH 512
#define NSEL 9
#define NLAYERS 3
#define LN_EPS 1e-5f

#define ADJ_WORDS 64
#define MTOT (BB*NN)        // 16384 rows
#define GRID 16             // 16x16 spatial bins
#define CW (1.0f/16.0f)
#define MAXD 64             // provable 2D kNN degree bound: 6k+k = 56 < 64

// ---------------- device scratch ----------------
__device__ uint32_t g_adj[BB * NN * ADJ_WORDS];     // 4 MB
__device__ float4   g_x4[BB * NN * (HH/4)];         // 32 MB current x (fp32, residual path)
__device__ __half   g_Ah[MTOT * HH];                // 16 MB agg fp16
__device__ __half   g_Wh[NLAYERS * HH * HH];        // W^T fp16  [l][n][k]
__device__ int      g_bin_start[BB][257];
__device__ uint16_t g_bin_ids[BB][NN];
__device__ uint16_t g_nbr[MTOT * MAXD];             // 2 MB CSR neighbor ids
__device__ int      g_deg[MTOT];

// ---------------- helpers (sm_80+ only) ----------------
__device__ __forceinline__ uint32_t smem_u32(const void* p) {
    uint32_t a;
    asm("{ .reg .u64 t; cvta.to.shared.u64 t, %1; cvt.u32.u64 %0, t; }" : "=r"(a) : "l"(p));
    return a;
}
__device__ __forceinline__ void ldm_x4(uint32_t* r, uint32_t addr) {
    asm volatile("ldmatrix.sync.aligned.m8n8.x4.shared.b16 {%0,%1,%2,%3}, [%4];"
                 : "=r"(r[0]), "=r"(r[1]), "=r"(r[2]), "=r"(r[3]) : "r"(addr));
}
__device__ __forceinline__ void mma_fp16(float* c, const uint32_t* a, const uint32_t* b) {
    asm volatile("mma.sync.aligned.m16n8k16.row.col.f32.f16.f16.f32 "
                 "{%0,%1,%2,%3}, {%4,%5,%6,%7}, {%8,%9}, {%0,%1,%2,%3};"
                 : "+f"(c[0]), "+f"(c[1]), "+f"(c[2]), "+f"(c[3])
                 : "r"(a[0]), "r"(a[1]), "r"(a[2]), "r"(a[3]), "r"(b[0]), "r"(b[1]));
}
__device__ __forceinline__ void cpa16(uint32_t s, const void* g) {
    asm volatile("cp.async.cg.shared.global [%0], [%1], 16;" :: "r"(s), "l"(g));
}

// ---------------- kernel 0: merged setup (zero adjacency + W transpose/fp16) ----
__global__ void __launch_bounds__(256) setup_kernel(const float* __restrict__ W) {
    __shared__ float tile[32][33];
    if (blockIdx.x < 128) {
        for (int j = blockIdx.x * 256 + threadIdx.x; j < BB * NN * ADJ_WORDS; j += 128 * 256)
            g_adj[j] = 0u;
        return;
    }
    const int bid = blockIdx.x - 128;
    const int l   = bid >> 8;
    const int rem = bid & 255;
    const int n0  = (rem & 15) * 32;
    const int k0  = (rem >> 4) * 32;
    const int tx  = threadIdx.x & 31;
    const int ty  = threadIdx.x >> 5;

    #pragma unroll
    for (int i = 0; i < 4; i++)
        tile[ty + i * 8][tx] = W[(size_t)l * HH * HH + (size_t)(k0 + ty + i * 8) * HH + n0 + tx];
    __syncthreads();

    #pragma unroll
    for (int i = 0; i < 4; i++) {
        const int n = n0 + ty + i * 8;
        const int k = k0 + tx;
        g_Wh[(size_t)l * HH * HH + (size_t)n * HH + k] = __float2half_rn(tile[tx][ty + i * 8]);
    }
}

// ---------------- kernel 1: spatial binning (one block per batch) ----------------
__global__ void __launch_bounds__(256) bin_kernel(const float2* __restrict__ coords) {
    __shared__ int cnt[256];
    __shared__ int start[257];
    __shared__ uint16_t cellof[NN];
    const int b = blockIdx.x;
    const int tid = threadIdx.x;

    cnt[tid] = 0;
    __syncthreads();
    for (int i = tid; i < NN; i += 256) {
        const float2 c = coords[(size_t)b * NN + i];
        int cx = (int)(c.x * GRID); cx = cx < 0 ? 0 : (cx > 15 ? 15 : cx);
        int cy = (int)(c.y * GRID); cy = cy < 0 ? 0 : (cy > 15 ? 15 : cy);
        const int cell = cy * GRID + cx;
        cellof[i] = (uint16_t)cell;
        atomicAdd(&cnt[cell], 1);
    }
    __syncthreads();
    if (tid == 0) {
        int run = 0;
        for (int c = 0; c < 256; c++) { start[c] = run; run += cnt[c]; }
        start[256] = run;
    }
    __syncthreads();
    g_bin_start[b][tid] = start[tid];
    if (tid == 0) g_bin_start[b][256] = start[256];
    cnt[tid] = start[tid];            // reuse as scatter cursor
    __syncthreads();
    for (int i = tid; i < NN; i += 256) {
        const int cell = cellof[i];
        const int pos = atomicAdd(&cnt[cell], 1);
        g_bin_ids[b][pos] = (uint16_t)i;
    }
}

// ---------------- kernel 2: binned exact top-k + adjacency ----------------
__global__ void __launch_bounds__(256) topk_adj_kernel(const float2* __restrict__ coords) {
    __shared__ float2 sc[NN];          // 16 KB
    __shared__ int sstart[257];
    __shared__ uint16_t sids[NN];      // 4 KB
    const int b   = blockIdx.y;
    const int seg = blockIdx.x;
    const int tid = threadIdx.x;

    const float2* cb = coords + (size_t)b * NN;
    for (int i = tid; i < NN; i += 256) { sc[i] = cb[i]; sids[i] = g_bin_ids[b][i]; }
    if (tid < 128) { sstart[2*tid] = g_bin_start[b][2*tid]; sstart[2*tid+1] = g_bin_start[b][2*tid+1]; }
    if (tid == 0) sstart[256] = g_bin_start[b][256];
    __syncthreads();

    const int n = seg * 256 + tid;
    const float xn = sc[n].x, yn = sc[n].y;
    const float sqn = __fadd_rn(__fmul_rn(xn, xn), __fmul_rn(yn, yn));
    int cx = (int)(xn * GRID); cx = cx < 0 ? 0 : (cx > 15 ? 15 : cx);
    int cy = (int)(yn * GRID); cy = cy < 0 ? 0 : (cy > 15 ? 15 : cy);

    unsigned long long top[NSEL];
    #pragma unroll
    for (int j = 0; j < NSEL; j++) top[j] = ~0ull;

    #define SCAN_CELL(yy, xx) do {                                                     \
        const int c_ = (yy) * GRID + (xx);                                             \
        const int e_ = sstart[c_ + 1];                                                 \
        for (int j_ = sstart[c_]; j_ < e_; j_++) {                                     \
            const int m_ = sids[j_];                                                   \
            const float xm_ = sc[m_].x, ym_ = sc[m_].y;                                \
            const float sqm_ = __fadd_rn(__fmul_rn(xm_, xm_), __fmul_rn(ym_, ym_));    \
            const float dot_ = __fmaf_rn(yn, ym_, __fmul_rn(xn, xm_));                 \
            const float d2_  = __fsub_rn(__fadd_rn(sqn, sqm_), __fmul_rn(2.0f, dot_)); \
            uint32_t fb_ = __float_as_uint(d2_);                                       \
            fb_ = (fb_ & 0x80000000u) ? ~fb_ : (fb_ | 0x80000000u);                    \
            const unsigned long long k_ = ((unsigned long long)fb_ << 32) | (uint32_t)m_; \
            if (k_ < top[NSEL - 1]) {                                                  \
                top[NSEL - 1] = k_;                                                    \
                _Pragma("unroll")                                                      \
                for (int q_ = NSEL - 1; q_ > 0; q_--) {                                \
                    if (top[q_] < top[q_ - 1]) {                                       \
                        unsigned long long t_ = top[q_];                               \
                        top[q_] = top[q_ - 1]; top[q_ - 1] = t_;                       \
                    }                                                                  \
                }                                                                      \
            }                                                                          \
        }                                                                              \
    } while (0)

    for (int r = 1; r <= GRID; r++) {
        const int x0 = (cx - r < 0) ? 0 : cx - r;
        const int x1 = (cx + r > 15) ? 15 : cx + r;
        if (r == 1) {
            const int y0 = (cy - 1 < 0) ? 0 : cy - 1;
            const int y1 = (cy + 1 > 15) ? 15 : cy + 1;
            for (int yy = y0; yy <= y1; yy++)
                for (int xx = x0; xx <= x1; xx++) SCAN_CELL(yy, xx);
        } else {
            if (cy - r >= 0)  for (int xx = x0; xx <= x1; xx++) SCAN_CELL(cy - r, xx);
            if (cy + r <= 15) for (int xx = x0; xx <= x1; xx++) SCAN_CELL(cy + r, xx);
            const int yi0 = (cy - r + 1 < 0) ? 0 : cy - r + 1;
            const int yi1 = (cy + r - 1 > 15) ? 15 : cy + r - 1;
            if (cx - r >= 0)  for (int yy = yi0; yy <= yi1; yy++) SCAN_CELL(yy, cx - r);
            if (cx + r <= 15) for (int yy = yi0; yy <= yi1; yy++) SCAN_CELL(yy, cx + r);
        }
        if (cx - r <= 0 && cx + r >= 15 && cy - r <= 0 && cy + r >= 15) break;
        float bnd = 1e30f;
        if (cx - r > 0)  bnd = fminf(bnd, xn - (float)(cx - r) * CW);
        if (cx + r < 15) bnd = fminf(bnd, (float)(cx + r + 1) * CW - xn);
        if (cy - r > 0)  bnd = fminf(bnd, yn - (float)(cy - r) * CW);
        if (cy + r < 15) bnd = fminf(bnd, (float)(cy + r + 1) * CW - yn);
        if (top[NSEL - 1] != ~0ull) {
            const uint32_t fb8 = (uint32_t)(top[NSEL - 1] >> 32);
            const float kd = (fb8 & 0x80000000u) ? __uint_as_float(fb8 ^ 0x80000000u)
                                                 : __uint_as_float(~fb8);
            if (kd < bnd * bnd - 1e-4f) break;
        }
    }

    #pragma unroll
    for (int rr = 1; rr < NSEL; rr++) {
        const int m = (int)(top[rr] & 0xffffffffu);
        atomicOr(&g_adj[((size_t)b * NN + n) * ADJ_WORDS + (m >> 5)], 1u << (m & 31));
        atomicOr(&g_adj[((size_t)b * NN + m) * ADJ_WORDS + (n >> 5)], 1u << (n & 31));
    }
}

// ---------------- kernel 3: bitmask -> fixed-width CSR, 4 threads/node ----------
// Each quad-thread scans a 16-word span; smem popc-prefix keeps global ascending
// (word,bit) order identical to the serial decode -> identical agg sum order.
__global__ void __launch_bounds__(256) adj2csr_kernel() {
    __shared__ int s_cnt[64][4];
    const int nl  = threadIdx.x >> 2;                 // node within block 0..63
    const int sub = threadIdx.x & 3;                  // span 0..3
    const int idx = blockIdx.x * 64 + nl;             // global node

    const uint4* row4 = (const uint4*)&g_adj[(size_t)idx * ADJ_WORDS + sub * 16];
    uint32_t w[16];
    int cnt = 0;
    #pragma unroll
    for (int q = 0; q < 4; q++) {
        const uint4 v = __ldg(&row4[q]);
        w[q*4+0] = v.x; w[q*4+1] = v.y; w[q*4+2] = v.z; w[q*4+3] = v.w;
        cnt += __popc(v.x) + __popc(v.y) + __popc(v.z) + __popc(v.w);
    }
    s_cnt[nl][sub] = cnt;
    __syncthreads();

    int off = 0;
    #pragma unroll
    for (int s = 0; s < 3; s++) if (s < sub) off += s_cnt[nl][s];
    const int total = s_cnt[nl][0] + s_cnt[nl][1] + s_cnt[nl][2] + s_cnt[nl][3];

    uint16_t* dst = &g_nbr[(size_t)idx * MAXD];
    #pragma unroll 4
    for (int ww = 0; ww < 16; ww++) {
        uint32_t bits = w[ww];
        const int wordbase = (sub * 16 + ww) << 5;
        while (bits) {
            const int bit = __ffs(bits) - 1;
            bits &= bits - 1;
            if (off < MAXD) dst[off] = (uint16_t)(wordbase + bit);
            off++;
        }
    }
    if (sub == 0) g_deg[idx] = (total < MAXD) ? total : MAXD;
}

// ---------------- kernel 4: CSR sparse aggregation (fp32 in, fp16 out) ----------
__global__ void __launch_bounds__(128) agg_kernel(const float4* __restrict__ xin) {
    __shared__ uint16_t s_nbr[MAXD];
    __shared__ int s_deg;
    const int b = blockIdx.y;
    const int n = blockIdx.x;
    const int t = threadIdx.x;
    const int idx = b * NN + n;

    if (t == 0) s_deg = g_deg[idx];
    if (t < MAXD) s_nbr[t] = g_nbr[(size_t)idx * MAXD + t];
    __syncthreads();

    const int deg = s_deg;
    const float4* xb = xin + (size_t)b * NN * (HH/4);
    float4 acc = make_float4(0.f, 0.f, 0.f, 0.f);
    #pragma unroll 4
    for (int i = 0; i < deg; i++) {
        const float4 v = __ldg(&xb[(size_t)s_nbr[i] * (HH/4) + t]);
        acc.x += v.x; acc.y += v.y; acc.z += v.z; acc.w += v.w;
    }

    __half2 h01 = __halves2half2(__float2half_rn(acc.x), __float2half_rn(acc.y));
    __half2 h23 = __halves2half2(__float2half_rn(acc.z), __float2half_rn(acc.w));
    const size_t base = ((size_t)b * NN + n) * (HH/2) + 2 * t;
    ((__half2*)g_Ah)[base]     = h01;
    ((__half2*)g_Ah)[base + 1] = h23;
}

// ---------------- kernel 5: cp.async-pipelined fp16 GEMM + LN, K-chunk 64 (R14) --
#define STG      82944
#define SG_BIAS  165888
#define SG_GAMMA 167936
#define SG_BETA  169984
#define SG_PSUM  172032
#define SG_PSQ   174080
#define SG_MU    176128
#define SG_RS    176384
#define SM_TOTAL2 176640

__global__ void __launch_bounds__(512, 1) gemm_mma_kernel(
    const __half* __restrict__ Ah,
    const __half* __restrict__ Wh,
    const float* __restrict__ bl, const float* __restrict__ gl, const float* __restrict__ btl,
    const float* __restrict__ resid, float* __restrict__ out)
{
    extern __shared__ char smem[];
    const uint32_t sbase = smem_u32(smem);
    const int tid  = threadIdx.x;
    const int lane = tid & 31;
    const int wid  = tid >> 5;
    const int mwarp = wid >> 3;
    const int nwarp = wid & 7;
    const int row0 = blockIdx.x * 64;

    ((float*)(smem + SG_BIAS))[tid]  = __ldg(&bl[tid]);
    ((float*)(smem + SG_GAMMA))[tid] = __ldg(&gl[tid]);
    ((float*)(smem + SG_BETA))[tid]  = __ldg(&btl[tid]);

    float c[16][4];
    #pragma unroll
    for (int f = 0; f < 16; f++)
        #pragma unroll
        for (int q = 0; q < 4; q++) c[f][q] = 0.f;

    #define LOAD_CHUNK(chk, stg) do {                                              \
        const int kc0_ = (chk) * 64;                                               \
        const uint32_t sb_ = sbase + (stg) * STG;                                  \
        {                                                                          \
            const int r_ = tid >> 3, seg_ = tid & 7;                               \
            cpa16(sb_ + r_ * 144 + seg_ * 16,                                      \
                  Ah + (size_t)(row0 + r_) * HH + kc0_ + seg_ * 8);                \
        }                                                                          \
        _Pragma("unroll")                                                          \
        for (int i_ = 0; i_ < 8; i_++) {                                           \
            const int idx_ = tid + i_ * 512;                                       \
            const int r_ = idx_ >> 3, seg_ = idx_ & 7;                             \
            cpa16(sb_ + 9216 + r_ * 144 + seg_ * 16,                               \
                  Wh + (size_t)r_ * HH + kc0_ + seg_ * 8);                         \
        }                                                                          \
        asm volatile("cp.async.commit_group;");                                    \
    } while (0)

    LOAD_CHUNK(0, 0);

    for (int chk = 0; chk < 8; chk++) {
        if (chk + 1 < 8) {
            LOAD_CHUNK(chk + 1, (chk + 1) & 1);
            asm volatile("cp.async.wait_group 1;");
        } else {
            asm volatile("cp.async.wait_group 0;");
        }
        __syncthreads();

        const uint32_t sb = sbase + (chk & 1) * STG;
        #pragma unroll
        for (int ks = 0; ks < 4; ks++) {
            const int amat = lane >> 3;
            const int arow = (amat & 1) * 8 + (lane & 7);
            const int akb  = (ks * 16 + (amat >> 1) * 8) * 2;
            uint32_t ah[2][4], bb[8][2];
            #pragma unroll
            for (int mi = 0; mi < 2; mi++) {
                const uint32_t ra = mwarp * 32 + mi * 16 + arow;
                ldm_x4(ah[mi], sb + ra * 144 + akb);
            }
            const int bmat = lane >> 3;
            const int bn   = (bmat >> 1) * 8 + (lane & 7);
            const int bkb  = (ks * 16 + (bmat & 1) * 8) * 2;
            #pragma unroll
            for (int g = 0; g < 4; g++) {
                uint32_t r[4];
                ldm_x4(r, sb + 9216 + (uint32_t)(nwarp * 64 + g * 16 + bn) * 144 + bkb);
                bb[g*2][0] = r[0]; bb[g*2][1] = r[1];
                bb[g*2+1][0] = r[2]; bb[g*2+1][1] = r[3];
            }
            #pragma unroll
            for (int mi = 0; mi < 2; mi++)
                #pragma unroll
                for (int ni = 0; ni < 8; ni++) mma_fp16(c[mi*8+ni], ah[mi], bb[ni]);
        }
        __syncthreads();
    }

    // ---------------- epilogue ----------------
    float* bias_s  = (float*)(smem + SG_BIAS);
    float* gamma_s = (float*)(smem + SG_GAMMA);
    float* beta_s  = (float*)(smem + SG_BETA);
    float* psum_s  = (float*)(smem + SG_PSUM);
    float* psq_s   = (float*)(smem + SG_PSQ);
    float* mu_s    = (float*)(smem + SG_MU);
    float* rs_s    = (float*)(smem + SG_RS);

    float ps[2][2] = {{0.f,0.f},{0.f,0.f}};
    float pq[2][2] = {{0.f,0.f},{0.f,0.f}};
    #pragma unroll
    for (int mi = 0; mi < 2; mi++)
        #pragma unroll
        for (int ni = 0; ni < 8; ni++) {
            const int f = mi*8 + ni;
            #pragma unroll
            for (int h = 0; h < 2; h++)
                #pragma unroll
                for (int j = 0; j < 2; j++) {
                    const int col = nwarp*64 + ni*8 + (lane & 3)*2 + j;
                    const float v = c[f][h*2+j] + bias_s[col];
                    c[f][h*2+j] = v;
                    ps[mi][h] += v;
                    pq[mi][h] += v * v;
                }
        }
    #pragma unroll
    for (int mi = 0; mi < 2; mi++)
        #pragma unroll
        for (int h = 0; h < 2; h++) {
            #pragma unroll
            for (int off = 1; off < 4; off <<= 1) {
                ps[mi][h] += __shfl_xor_sync(0xffffffffu, ps[mi][h], off);
                pq[mi][h] += __shfl_xor_sync(0xffffffffu, pq[mi][h], off);
            }
        }
    if ((lane & 3) == 0) {
        #pragma unroll
        for (int mi = 0; mi < 2; mi++)
            #pragma unroll
            for (int h = 0; h < 2; h++) {
                const int rl = mwarp*32 + mi*16 + h*8 + (lane >> 2);
                psum_s[rl*8 + nwarp] = ps[mi][h];
                psq_s [rl*8 + nwarp] = pq[mi][h];
            }
    }
    __syncthreads();
    if (tid < 64) {
        float s = 0.f, q = 0.f;
        #pragma unroll
        for (int w = 0; w < 8; w++) { s += psum_s[tid*8 + w]; q += psq_s[tid*8 + w]; }
        const float mu = s * (1.0f / HH);
        const float var = q * (1.0f / HH) - mu * mu;
        mu_s[tid] = mu;
        rs_s[tid] = rsqrtf(var + LN_EPS);
    }
    __syncthreads();

    #pragma unroll
    for (int mi = 0; mi < 2; mi++)
        #pragma unroll
        for (int h = 0; h < 2; h++) {
            const int rl = mwarp*32 + mi*16 + h*8 + (lane >> 2);
            const int grow = row0 + rl;
            const float mu = mu_s[rl];
            const float rs = rs_s[rl];
            #pragma unroll
            for (int ni = 0; ni < 8; ni++) {
                const int f = mi*8 + ni;
                const int col = nwarp*64 + ni*8 + (lane & 3)*2;
                float2 o;
                o.x = fmaxf((c[f][h*2+0] - mu) * rs * gamma_s[col]   + beta_s[col],   0.f);
                o.y = fmaxf((c[f][h*2+1] - mu) * rs * gamma_s[col+1] + beta_s[col+1], 0.f);
                if (resid != nullptr) {
                    const float2 rv = __ldg((const float2*)&resid[(size_t)grow * HH + col]);
                    o.x += rv.x; o.y += rv.y;
                }
                *(float2*)&out[(size_t)grow * HH + col] = o;
            }
        }
}

// ---------------- launcher ----------------
extern "C" void kernel_launch(void* const* d_in, const int* in_sizes, int n_in,
                              void* d_out, int out_size) {
    (void)in_sizes; (void)n_in; (void)out_size;
    const float*  node_features = (const float*)d_in[0];   // [8,2048,512]
    const float2* coords        = (const float2*)d_in[1];  // [8,2048,2]
    const float*  W             = (const float*)d_in[2];   // [3,512,512]
    const float*  bvec          = (const float*)d_in[3];   // [3,512]
    const float*  gamma         = (const float*)d_in[4];   // [3,512]
    const float*  beta          = (const float*)d_in[5];   // [3,512]
    float*        outp          = (float*)d_out;           // [8,2048,512]

    float4* gx;  cudaGetSymbolAddress((void**)&gx,  g_x4);
    __half *ah, *wh;
    cudaGetSymbolAddress((void**)&ah, g_Ah);
    cudaGetSymbolAddress((void**)&wh, g_Wh);

    cudaFuncSetAttribute(gemm_mma_kernel, cudaFuncAttributeMaxDynamicSharedMemorySize, SM_TOTAL2);

    setup_kernel<<<896, 256>>>(W);
    bin_kernel<<<BB, 256>>>(coords);
    topk_adj_kernel<<<dim3(NN / 256, BB), 256>>>(coords);
    adj2csr_kernel<<<MTOT / 64, 256>>>();

    for (int l = 0; l < NLAYERS; l++) {
        const float4* xin = (l == 0) ? (const float4*)node_features : (const float4*)gx;
        agg_kernel<<<dim3(NN, BB), 128>>>(xin);

        const float* resid = (l == 0) ? nullptr : (const float*)gx;
        float* out = (l == NLAYERS - 1) ? outp : (float*)gx;
        gemm_mma_kernel<<<MTOT / 64, 512, SM_TOTAL2>>>(
            ah, wh + (size_t)l * HH * HH,
            bvec + (size_t)l * HH, gamma + (size_t)l * HH, beta + (size_t)l * HH,
            resid, out);
    }
}